// round 12
// baseline (speedup 1.0000x reference)
#include <cuda_runtime.h>
#include <cuda_fp16.h>
#include <math.h>
#include <stdint.h>

#define Bq 2
#define Sq 2048
#define Dq 512
#define Hq 8

#define SDc  ((long)Sq * Dq)
#define SSc  ((long)Sq * Sq)
#define DDc  ((long)Dq * Dq)

#define X_PLANE    ((long)Bq * Sq * Dq)
#define W_PLANE    ((long)Hq * Dq * Dq)
#define QK_PLANE   ((long)Bq * Hq * Sq * Dq)
#define ATTN_PLANE ((long)Bq * Hq * Sq * Sq)
#define Z_PLANE    QK_PLANE

__device__ __align__(256) float g_attn[ATTN_PLANE];
__device__ __align__(256) __half g_xq [2 * X_PLANE];
__device__ __align__(256) __half g_xk [2 * X_PLANE];
__device__ __align__(256) __half g_xv [2 * X_PLANE];
__device__ __align__(256) __half g_wqt[2 * W_PLANE];
__device__ __align__(256) __half g_wkt[2 * W_PLANE];
__device__ __align__(256) __half g_wvt[2 * W_PLANE];
__device__ __align__(256) __half g_wzt[2 * W_PLANE];
__device__ __align__(256) __half g_qs [2 * QK_PLANE];
__device__ __align__(256) __half g_ks [2 * QK_PLANE];
__device__ __align__(256) __half g_vts[2 * QK_PLANE];   // [b,h,e,s], hi plane used
__device__ __align__(256) __half g_zs [2 * Z_PLANE];    // [b,s,h*D], hi plane used
__device__ __align__(256) float g_m [(long)Bq * Hq * Sq];   // row max
__device__ __align__(256) float g_ti[(long)Bq * Hq * Sq];   // 1024 / row sumexp

struct Off { int dv; long s1; int md; long s2; };

__device__ __forceinline__ uint32_t smem_u32(const void* p) {
    uint32_t a;
    asm("{ .reg .u64 t; cvta.to.shared.u64 t, %1; cvt.u32.u64 %0, t; }" : "=r"(a) : "l"(p));
    return a;
}
__device__ __forceinline__ void cpasync16(uint32_t dst, const void* src) {
    asm volatile("cp.async.cg.shared.global [%0], [%1], 16;" :: "r"(dst), "l"(src) : "memory");
}
#define CP_COMMIT() asm volatile("cp.async.commit_group;" ::: "memory")
#define CP_WAIT1()  asm volatile("cp.async.wait_group 1;" ::: "memory")
#define CP_WAIT0()  asm volatile("cp.async.wait_group 0;" ::: "memory")

#define LDSM4(r, a) \
    asm volatile("ldmatrix.sync.aligned.m8n8.x4.shared.b16 {%0,%1,%2,%3}, [%4];" \
        : "=r"((r)[0]), "=r"((r)[1]), "=r"((r)[2]), "=r"((r)[3]) : "r"(a))

#define MMAF(c, a, b0, b1) \
    asm volatile("mma.sync.aligned.m16n8k16.row.col.f32.f16.f16.f32 " \
        "{%0,%1,%2,%3},{%4,%5,%6,%7},{%8,%9},{%0,%1,%2,%3};" \
        : "+f"((c)[0]), "+f"((c)[1]), "+f"((c)[2]), "+f"((c)[3]) \
        : "r"((a)[0]), "r"((a)[1]), "r"((a)[2]), "r"((a)[3]), "r"(b0), "r"(b1))

#define MMAH(c, a, b0, b1) \
    asm volatile("mma.sync.aligned.m16n8k16.row.col.f16.f16.f16.f16 " \
        "{%0,%1},{%2,%3,%4,%5},{%6,%7},{%0,%1};" \
        : "+r"((c)[0]), "+r"((c)[1]) \
        : "r"((a)[0]), "r"((a)[1]), "r"((a)[2]), "r"((a)[3]), "r"(b0), "r"(b1))

__device__ __forceinline__ void split1(float x, __half& h, __half& l) {
    h = __float2half_rn(x);
    l = __float2half_rn(x - __half2float(h));
}
__device__ __forceinline__ uint32_t pack2(__half a, __half b) {
    __half2 t; t.x = a; t.y = b;
    return *reinterpret_cast<uint32_t*>(&t);
}
__device__ __forceinline__ void sts8(uint32_t addr, uint32_t x, uint32_t y) {
    asm volatile("st.shared.v2.b32 [%0], {%1,%2};" :: "r"(addr), "r"(x), "r"(y) : "memory");
}

#define STAGE_B  16384
#define STAGE_SZ 32768
#define NSTAGE   3
#define SMEM_SZ  (NSTAGE * STAGE_SZ)
#define GTHREADS 512

// ---------------------------------------------------------------------------
// fp16 HMMA TN GEMM (unchanged from R11).
// ---------------------------------------------------------------------------
template <int PMASK>
__global__ void __launch_bounds__(GTHREADS, 1)
gemm_mma(const __half* __restrict__ A, long aplane,
         const __half* __restrict__ B, long bplane,
         void* Cv, long cplane,
         int K, int lda, int ldb, int ldc,
         Off oa, Off ob, Off oc,
         float alpha, const float* __restrict__ bias, int mode, int writeLo)
{
    constexpr bool needBlo = (PMASK & 1) != 0;
    constexpr bool needAlo = (PMASK & 2) != 0;

    extern __shared__ char smem[];
    const uint32_t sm = smem_u32(smem);
    const int tid = threadIdx.x, wid = tid >> 5, lane = tid & 31;
    const int z = blockIdx.z;

    const __half* Ahp = A + (long)(z / oa.dv) * oa.s1 + (long)(z % oa.md) * oa.s2;
    const __half* Bhp = B + (long)(z / ob.dv) * ob.s1 + (long)(z % ob.md) * ob.s2;
    const long coff = (long)(z / oc.dv) * oc.s1 + (long)(z % oc.md) * oc.s2;

    const long row0 = (long)blockIdx.y * 128;
    const long col0 = (long)blockIdx.x * 128;

    const int lrow = tid >> 2;
    const int c0   = (tid & 3) * 2;
    const int lpl  = c0 >> 2;
    const __half* Asrc = (lpl ? Ahp + aplane : Ahp) + (row0 + lrow) * lda + (c0 & 3) * 8;
    const __half* Bsrc = (lpl ? Bhp + bplane : Bhp) + (col0 + lrow) * ldb + (c0 & 3) * 8;
    const bool doA = (lpl == 0) || needAlo;
    const bool doB = (lpl == 0) || needBlo;
    uint32_t soff[2];
    #pragma unroll
    for (int j = 0; j < 2; ++j)
        soff[j] = lrow * 128 + (((c0 + j) ^ (lrow & 7)) << 4);

    const int wm = wid & 3, wn = wid >> 2;
    const int g = lane >> 3, r8 = lane & 7;
    const int a_roff = ((g & 1) << 3) + r8;
    const int a_kh   = g >> 1;
    const int b_roff = ((g >> 1) << 3) + r8;
    const int b_kh   = g & 1;

    uint32_t a_row[2], a_rx[2];
    #pragma unroll
    for (int mt = 0; mt < 2; ++mt) {
        const int row = wm * 32 + mt * 16 + a_roff;
        a_row[mt] = row * 128;
        a_rx[mt] = row & 7;
    }
    uint32_t b_row[2], b_rx[2];
    #pragma unroll
    for (int np = 0; np < 2; ++np) {
        const int row = wn * 32 + np * 16 + b_roff;
        b_row[np] = row * 128;
        b_rx[np] = row & 7;
    }

    float acc[2][4][4];
    uint32_t acch[2][4][2];
    #pragma unroll
    for (int i = 0; i < 2; ++i)
        #pragma unroll
        for (int j = 0; j < 4; ++j) {
            #pragma unroll
            for (int q = 0; q < 4; ++q) acc[i][j][q] = 0.0f;
            acch[i][j][0] = 0u; acch[i][j][1] = 0u;
        }

    const int nst = K / 32;

    #pragma unroll
    for (int p = 0; p < 2; ++p) {
        if (p < nst) {
            const uint32_t tb = sm + p * STAGE_SZ;
            const long k0 = (long)p * 32;
            #pragma unroll
            for (int j = 0; j < 2; ++j) {
                if (doA) cpasync16(tb + soff[j], Asrc + k0 + j * 8);
                if (doB) cpasync16(tb + STAGE_B + soff[j], Bsrc + k0 + j * 8);
            }
        }
        CP_COMMIT();
    }

    int stg = 0;
    for (int s = 0; s < nst; ++s) {
        if (s + 1 < nst) CP_WAIT1(); else CP_WAIT0();
        __syncthreads();

        const uint32_t tb = sm + stg * STAGE_SZ;
        const uint32_t tba = tb, tbb = tb + STAGE_B;

        #pragma unroll
        for (int ks = 0; ks < 2; ++ks) {
            const int ca = ks * 2 + a_kh;
            const int cb = ks * 2 + b_kh;

            uint32_t Ahr[2][4], Bhr[2][4];
            #pragma unroll
            for (int mt = 0; mt < 2; ++mt)
                LDSM4(Ahr[mt], tba + a_row[mt] + ((ca ^ a_rx[mt]) << 4));
            #pragma unroll
            for (int np = 0; np < 2; ++np)
                LDSM4(Bhr[np], tbb + b_row[np] + ((cb ^ b_rx[np]) << 4));
            #pragma unroll
            for (int mt = 0; mt < 2; ++mt)
                #pragma unroll
                for (int nt = 0; nt < 4; ++nt) {
                    const int np = nt >> 1, s2 = (nt & 1) * 2;
                    MMAF(acc[mt][nt], Ahr[mt], Bhr[np][s2], Bhr[np][s2 + 1]);
                }

            if (needBlo) {
                uint32_t Blr[2][4];
                #pragma unroll
                for (int np = 0; np < 2; ++np)
                    LDSM4(Blr[np], tbb + b_row[np] + (((cb + 4) ^ b_rx[np]) << 4));
                #pragma unroll
                for (int mt = 0; mt < 2; ++mt)
                    #pragma unroll
                    for (int nt = 0; nt < 4; ++nt) {
                        const int np = nt >> 1, s2 = (nt & 1) * 2;
                        MMAH(acch[mt][nt], Ahr[mt], Blr[np][s2], Blr[np][s2 + 1]);
                    }
            }

            if (needAlo) {
                uint32_t Alr[2][4];
                #pragma unroll
                for (int mt = 0; mt < 2; ++mt)
                    LDSM4(Alr[mt], tba + a_row[mt] + (((ca + 4) ^ a_rx[mt]) << 4));
                #pragma unroll
                for (int mt = 0; mt < 2; ++mt)
                    #pragma unroll
                    for (int nt = 0; nt < 4; ++nt) {
                        const int np = nt >> 1, s2 = (nt & 1) * 2;
                        MMAH(acch[mt][nt], Alr[mt], Bhr[np][s2], Bhr[np][s2 + 1]);
                    }
            }
        }

        if (s + 2 < nst) {
            int ps = stg + 2; if (ps >= NSTAGE) ps -= NSTAGE;
            const uint32_t pb = sm + ps * STAGE_SZ;
            const long k0 = (long)(s + 2) * 32;
            #pragma unroll
            for (int j = 0; j < 2; ++j) {
                if (doA) cpasync16(pb + soff[j], Asrc + k0 + j * 8);
                if (doB) cpasync16(pb + STAGE_B + soff[j], Bsrc + k0 + j * 8);
            }
        }
        CP_COMMIT();

        if (++stg == NSTAGE) stg = 0;
    }

    const int r_in = lane >> 2, c_in = (lane & 3) * 2;
    #pragma unroll
    for (int mt = 0; mt < 2; ++mt) {
        #pragma unroll
        for (int half = 0; half < 2; ++half) {
            const long row = row0 + wm * 32 + mt * 16 + half * 8 + r_in;
            #pragma unroll
            for (int nt = 0; nt < 4; ++nt) {
                const int colg = (int)col0 + wn * 32 + nt * 8 + c_in;
                float v0 = acc[mt][nt][half * 2 + 0];
                float v1 = acc[mt][nt][half * 2 + 1];
                if (PMASK) {
                    float2 cf = __half22float2(*reinterpret_cast<__half2*>(&acch[mt][nt][half]));
                    v0 += cf.x;
                    v1 += cf.y;
                }
                v0 *= alpha;
                v1 *= alpha;
                if (mode == 0) {
                    if (bias) { v0 += bias[colg]; v1 += bias[colg + 1]; }
                    *(float2*)((float*)Cv + coff + row * ldc + colg) = make_float2(v0, v1);
                } else if (mode == 1) {
                    __half h0, l0, h1, l1;
                    split1(v0, h0, l0); split1(v1, h1, l1);
                    __half* Ch = (__half*)Cv + coff + row * ldc + colg;
                    *(__half2*)Ch = *(__half2*)&(uint32_t&)*(uint32_t[]){pack2(h0, h1)};
                    if (writeLo) {
                        uint32_t lw = pack2(l0, l1);
                        *(uint32_t*)(Ch + cplane) = lw;
                    }
                } else {
                    __half h0, l0, h1, l1;
                    split1(v0, h0, l0); split1(v1, h1, l1);
                    __half* Ch = (__half*)Cv + coff;
                    const long o0 = (long)colg * ldc + row;
                    const long o1 = (long)(colg + 1) * ldc + row;
                    Ch[o0] = h0;
                    Ch[o1] = h1;
                    if (writeLo) {
                        Ch[o0 + cplane] = l0;
                        Ch[o1 + cplane] = l1;
                    }
                }
            }
        }
    }
}

// ---------------------------------------------------------------------------
// PV kernel: A = softmax probs computed on the fly from fp32 scores + row stats.
// Block tile 64x256, K-chunk 32, 16 warps (warp m16 x n64), 3-stage pipeline.
// Passes: P_hi.V_hi (f32acc) + P_lo.V_hi (f16acc). Output z_s hi to g_zs.
// ---------------------------------------------------------------------------
#define PV_BB   8192
#define PV_STG  40960
#define PV_SMEM (3 * PV_STG)

__global__ void __launch_bounds__(512, 1)
pv_kernel(const float* __restrict__ S, const __half* __restrict__ V,
          __half* __restrict__ Z)
{
    extern __shared__ char smem[];
    const uint32_t sm = smem_u32(smem);
    const int tid = threadIdx.x, wid = tid >> 5, lane = tid & 31;
    const int z = blockIdx.z;
    const long row0 = (long)blockIdx.y * 64;
    const long col0 = (long)blockIdx.x * 256;

    // A loader: thread -> (row, 4 consecutive score cols)
    const int ar  = tid >> 3;            // 0..63
    const int seg = tid & 7;             // 0..7
    const long rowg = row0 + ar;
    const float* Sp = S + (long)z * SSc + rowg * Sq + seg * 4;
    const float m  = g_m [(long)z * Sq + rowg];
    const float ti = g_ti[(long)z * Sq + rowg];
    const uint32_t a_hi = ar * 128 + ((((seg >> 1) + 0) ^ (ar & 7)) << 4) + (seg & 1) * 8;
    const uint32_t a_lo = ar * 128 + ((((seg >> 1) + 4) ^ (ar & 7)) << 4) + (seg & 1) * 8;

    // B loader: thread -> (V row, 2 chunks of 16B)
    const int br = tid >> 1;             // 0..255
    const int bc = (tid & 1) * 2;        // chunk 0 or 2
    const __half* Vp = V + (long)z * SDc + (col0 + br) * Sq;
    const uint32_t b_s0 = br * 128 + (((bc + 0) ^ (br & 7)) << 4);
    const uint32_t b_s1 = br * 128 + (((bc + 1) ^ (br & 7)) << 4);
    const int bko = bc * 8;

    // compute mapping: 4m x 4n warps
    const int wm = wid & 3, wn = wid >> 2;
    const int g = lane >> 3, r8 = lane & 7;
    const int a_roff = ((g & 1) << 3) + r8;
    const int a_kh   = g >> 1;
    const int b_roff = ((g >> 1) << 3) + r8;
    const int b_kh   = g & 1;

    const int arc = wm * 16 + a_roff;
    const uint32_t a_rowb = arc * 128;
    const uint32_t a_rx = arc & 7;
    uint32_t b_rowb[4], b_rx[4];
    #pragma unroll
    for (int np = 0; np < 4; ++np) {
        const int row = wn * 64 + np * 16 + b_roff;
        b_rowb[np] = row * 128;
        b_rx[np] = row & 7;
    }

    float acc[8][4];
    uint32_t acch[8][2];
    #pragma unroll
    for (int j = 0; j < 8; ++j) {
        #pragma unroll
        for (int q = 0; q < 4; ++q) acc[j][q] = 0.0f;
        acch[j][0] = 0u; acch[j][1] = 0u;
    }

    const int nst = Sq / 32;   // 64

    // prologue: stages 0,1
    #pragma unroll
    for (int p = 0; p < 2; ++p) {
        const uint32_t tb = sm + p * PV_STG;
        const long k0 = (long)p * 32;
        cpasync16(tb + PV_BB + b_s0, Vp + k0 + bko);
        cpasync16(tb + PV_BB + b_s1, Vp + k0 + bko + 8);
        CP_COMMIT();
        float4 sv = *(const float4*)(Sp + k0);
        float p0 = __expf(sv.x - m) * ti, p1 = __expf(sv.y - m) * ti;
        float p2 = __expf(sv.z - m) * ti, p3 = __expf(sv.w - m) * ti;
        __half h0, l0, h1, l1, h2, l2, h3, l3;
        split1(p0, h0, l0); split1(p1, h1, l1);
        split1(p2, h2, l2); split1(p3, h3, l3);
        sts8(tb + a_hi, pack2(h0, h1), pack2(h2, h3));
        sts8(tb + a_lo, pack2(l0, l1), pack2(l2, l3));
    }

    int stg = 0;
    #pragma unroll 1
    for (int s = 0; s < nst; ++s) {
        if (s + 1 < nst) CP_WAIT1(); else CP_WAIT0();
        __syncthreads();

        // issue next-next loads early (LDG latency hidden under MMA)
        const bool pf = (s + 2 < nst);
        int ps = stg + 2; if (ps >= NSTAGE) ps -= NSTAGE;
        const uint32_t pb = sm + ps * PV_STG;
        float4 sv;
        if (pf) {
            const long k2 = (long)(s + 2) * 32;
            cpasync16(pb + PV_BB + b_s0, Vp + k2 + bko);
            cpasync16(pb + PV_BB + b_s1, Vp + k2 + bko + 8);
            sv = *(const float4*)(Sp + k2);
        }

        const uint32_t tb = sm + stg * PV_STG;
        #pragma unroll
        for (int ks = 0; ks < 2; ++ks) {
            const int ca = ks * 2 + a_kh;
            const int cb = ks * 2 + b_kh;
            uint32_t Ah[4], Al[4], Bh[4][4];
            LDSM4(Ah, tb + a_rowb + (((ca + 0) ^ a_rx) << 4));
            LDSM4(Al, tb + a_rowb + (((ca + 4) ^ a_rx) << 4));
            #pragma unroll
            for (int np = 0; np < 4; ++np)
                LDSM4(Bh[np], tb + PV_BB + b_rowb[np] + ((cb ^ b_rx[np]) << 4));
            #pragma unroll
            for (int nt = 0; nt < 8; ++nt) {
                const int np = nt >> 1, s2 = (nt & 1) * 2;
                MMAF(acc[nt], Ah, Bh[np][s2], Bh[np][s2 + 1]);
            }
            #pragma unroll
            for (int nt = 0; nt < 8; ++nt) {
                const int np = nt >> 1, s2 = (nt & 1) * 2;
                MMAH(acch[nt], Al, Bh[np][s2], Bh[np][s2 + 1]);
            }
        }

        if (pf) {
            float p0 = __expf(sv.x - m) * ti, p1 = __expf(sv.y - m) * ti;
            float p2 = __expf(sv.z - m) * ti, p3 = __expf(sv.w - m) * ti;
            __half h0, l0, h1, l1, h2, l2, h3, l3;
            split1(p0, h0, l0); split1(p1, h1, l1);
            split1(p2, h2, l2); split1(p3, h3, l3);
            sts8(pb + a_hi, pack2(h0, h1), pack2(h2, h3));
            sts8(pb + a_lo, pack2(l0, l1), pack2(l2, l3));
        }
        CP_COMMIT();

        if (++stg == NSTAGE) stg = 0;
    }

    // epilogue: z_s = acc/128, hi fp16, concat layout
    const int r_in = lane >> 2, c_in = (lane & 3) * 2;
    __half* Zb = Z + (long)(z / Hq) * Sq * (Hq * Dq) + (long)(z % Hq) * Dq;
    #pragma unroll
    for (int half = 0; half < 2; ++half) {
        const long row = row0 + wm * 16 + half * 8 + r_in;
        #pragma unroll
        for (int nt = 0; nt < 8; ++nt) {
            const int colg = (int)col0 + wn * 64 + nt * 8 + c_in;
            float2 cf = __half22float2(*reinterpret_cast<__half2*>(&acch[nt][half]));
            float v0 = (acc[nt][half * 2 + 0] + cf.x) * (1.0f / 128.0f);
            float v1 = (acc[nt][half * 2 + 1] + cf.y) * (1.0f / 128.0f);
            uint32_t hw = pack2(__float2half_rn(v0), __float2half_rn(v1));
            *(uint32_t*)(Zb + row * (Hq * Dq) + colg) = hw;
        }
    }
}

// ---------------------------------------------------------------------------
template <bool WLO>
__global__ void __launch_bounds__(256) split_kernel(const float* __restrict__ in,
                                                    __half* __restrict__ hi, long plane,
                                                    float scale)
{
    const long idx = (long)blockIdx.x * 256 + threadIdx.x;
    float4 v = ((const float4*)in)[idx];
    __half h0, l0, h1, l1, h2, l2, h3, l3;
    split1(v.x * scale, h0, l0); split1(v.y * scale, h1, l1);
    split1(v.z * scale, h2, l2); split1(v.w * scale, h3, l3);
    ((uint32_t*)hi)[2 * idx]     = pack2(h0, h1);
    ((uint32_t*)hi)[2 * idx + 1] = pack2(h2, h3);
    if (WLO) {
        ((uint32_t*)(hi + plane))[2 * idx]     = pack2(l0, l1);
        ((uint32_t*)(hi + plane))[2 * idx + 1] = pack2(l2, l3);
    }
}

template <bool WLO>
__global__ void __launch_bounds__(256) tsplit_kernel(const float* __restrict__ in,
                                                     __half* __restrict__ outh,
                                                     long plane, int R, int C, float scale)
{
    __shared__ float ts[32][33];
    const int tx = threadIdx.x, ty = threadIdx.y;
    const long zo = (long)blockIdx.z * R * C;
    const int r0 = blockIdx.y * 32, c0 = blockIdx.x * 32;
    #pragma unroll
    for (int i = 0; i < 4; ++i)
        ts[ty + 8 * i][tx] = in[zo + (long)(r0 + ty + 8 * i) * C + c0 + tx];
    __syncthreads();
    #pragma unroll
    for (int i = 0; i < 4; ++i) {
        __half h, l;
        split1(ts[tx][ty + 8 * i] * scale, h, l);
        const long o = zo + (long)(c0 + ty + 8 * i) * R + r0 + tx;
        outh[o] = h;
        if (WLO) outh[o + plane] = l;
    }
}

// ---------------------------------------------------------------------------
// stats + avg: per (b, q-row), all 8 heads staged in smem.
// Writes per-head (m, 1024/t) and attn_avg. No prob matrix write.
// ---------------------------------------------------------------------------
__global__ void __launch_bounds__(256) stats_avg_kernel(float* __restrict__ avg_out)
{
    extern __shared__ float srows[];   // 8 * 2048 floats
    __shared__ float sr[8];
    const int r = blockIdx.x & (Sq - 1);
    const int b = blockIdx.x >> 11;
    const int tid = threadIdx.x;

    #pragma unroll 1
    for (int h = 0; h < Hq; ++h) {
        const float* p = g_attn + (((long)b * Hq + h) * Sq + r) * Sq;
        #pragma unroll
        for (int i = 0; i < 8; ++i)
            srows[h * Sq + tid + i * 256] = p[tid + i * 256];
    }
    __syncthreads();

    float invt[Hq];
    #pragma unroll 1
    for (int h = 0; h < Hq; ++h) {
        float mx = -1e30f;
        #pragma unroll
        for (int i = 0; i < 8; ++i) mx = fmaxf(mx, srows[h * Sq + tid + i * 256]);
        #pragma unroll
        for (int o = 16; o > 0; o >>= 1) mx = fmaxf(mx, __shfl_xor_sync(~0u, mx, o));
        if ((tid & 31) == 0) sr[tid >> 5] = mx;
        __syncthreads();
        float mm = sr[0];
        #pragma unroll
        for (int i = 1; i < 8; ++i) mm = fmaxf(mm, sr[i]);
        __syncthreads();

        float s = 0.f;
        #pragma unroll
        for (int i = 0; i < 8; ++i) {
            float e = __expf(srows[h * Sq + tid + i * 256] - mm);
            srows[h * Sq + tid + i * 256] = e;
            s += e;
        }
        #pragma unroll
        for (int o = 16; o > 0; o >>= 1) s += __shfl_xor_sync(~0u, s, o);
        if ((tid & 31) == 0) sr[tid >> 5] = s;
        __syncthreads();
        float t = 0.f;
        #pragma unroll
        for (int i = 0; i < 8; ++i) t += sr[i];
        invt[h] = 1.0f / t;
        if (tid == 0) {
            g_m [((long)b * Hq + h) * Sq + r] = mm;
            g_ti[((long)b * Hq + h) * Sq + r] = 1024.0f / t;
        }
        __syncthreads();
    }

    float* dst = avg_out + ((long)b * Sq + r) * Sq;
    #pragma unroll
    for (int i = 0; i < 8; ++i) {
        float a = 0.f;
        #pragma unroll
        for (int h = 0; h < Hq; ++h)
            a += srows[h * Sq + tid + i * 256] * invt[h];
        dst[tid + i * 256] = a * 0.125f;
    }
}

// ---------------------------------------------------------------------------
extern "C" void kernel_launch(void* const* d_in, const int* in_sizes, int n_in,
                              void* d_out, int out_size)
{
    (void)in_sizes; (void)n_in; (void)out_size;
    const float* Xq = (const float*)d_in[0];
    const float* Xk = (const float*)d_in[1];
    const float* Xv = (const float*)d_in[2];
    const float* Wq = (const float*)d_in[3];
    const float* Wk = (const float*)d_in[4];
    const float* Wv = (const float*)d_in[5];
    const float* Wz = (const float*)d_in[6];
    const float* bz = (const float*)d_in[7];
    float* out = (float*)d_out;
    float* attn_avg = out + (long)Bq * Sq * Dq;

    __half *pxq, *pxk, *pxv, *pwq, *pwk, *pwv, *pwz, *pqs, *pks, *pvt, *pzs;
    float* pattn;
    cudaGetSymbolAddress((void**)&pxq, g_xq);
    cudaGetSymbolAddress((void**)&pxk, g_xk);
    cudaGetSymbolAddress((void**)&pxv, g_xv);
    cudaGetSymbolAddress((void**)&pwq, g_wqt);
    cudaGetSymbolAddress((void**)&pwk, g_wkt);
    cudaGetSymbolAddress((void**)&pwv, g_wvt);
    cudaGetSymbolAddress((void**)&pwz, g_wzt);
    cudaGetSymbolAddress((void**)&pqs, g_qs);
    cudaGetSymbolAddress((void**)&pks, g_ks);
    cudaGetSymbolAddress((void**)&pvt, g_vts);
    cudaGetSymbolAddress((void**)&pzs, g_zs);
    cudaGetSymbolAddress((void**)&pattn, g_attn);

    cudaFuncSetAttribute(gemm_mma<0>, cudaFuncAttributeMaxDynamicSharedMemorySize, SMEM_SZ);
    cudaFuncSetAttribute(gemm_mma<1>, cudaFuncAttributeMaxDynamicSharedMemorySize, SMEM_SZ);
    cudaFuncSetAttribute(pv_kernel, cudaFuncAttributeMaxDynamicSharedMemorySize, PV_SMEM);
    cudaFuncSetAttribute(stats_avg_kernel, cudaFuncAttributeMaxDynamicSharedMemorySize, 65536);

    const float inv4 = (float)(1.0 / pow((double)Dq, 0.25));

    // 1) convert inputs/weights to fp16 (hi planes only; Wz keeps lo)
    {
        int nb = (int)(X_PLANE / 1024);
        split_kernel<false><<<nb, 256>>>(Xq, pxq, X_PLANE, 1.0f);
        split_kernel<false><<<nb, 256>>>(Xk, pxk, X_PLANE, 1.0f);
        split_kernel<false><<<nb, 256>>>(Xv, pxv, X_PLANE, 1.0f);
        dim3 tb(32, 8);
        tsplit_kernel<false><<<dim3(16, 16, 8), tb>>>(Wq, pwq, W_PLANE, Dq, Dq, 16.0f);
        tsplit_kernel<false><<<dim3(16, 16, 8), tb>>>(Wk, pwk, W_PLANE, Dq, Dq, 16.0f);
        tsplit_kernel<false><<<dim3(16, 16, 8), tb>>>(Wv, pwv, W_PLANE, Dq, Dq, 16.0f);
        tsplit_kernel<true><<<dim3(16, 128, 1), tb>>>(Wz, pwz, W_PLANE, Hq * Dq, Dq, 64.0f);
    }

    // 2) projections (TN), single hi-pass. q_s/k_s = 4x true, v_s = 4x v.
    {
        dim3 grid(Dq / 128, Sq / 128, Bq * Hq);
        Off oa = { Hq, SDc, 1, 0 };
        Off ob = { 1, 0, Hq, DDc };
        Off oc = { 1, SDc, 1, 0 };
        gemm_mma<0><<<grid, GTHREADS, SMEM_SZ>>>(pxq, X_PLANE, pwq, W_PLANE, pqs, QK_PLANE,
                                                 Dq, Dq, Dq, Dq, oa, ob, oc, inv4 * 0.25f, nullptr, 1, 0);
        gemm_mma<0><<<grid, GTHREADS, SMEM_SZ>>>(pxk, X_PLANE, pwk, W_PLANE, pks, QK_PLANE,
                                                 Dq, Dq, Dq, Dq, oa, ob, oc, inv4 * 0.25f, nullptr, 1, 0);
        gemm_mma<0><<<grid, GTHREADS, SMEM_SZ>>>(pxv, X_PLANE, pwv, W_PLANE, pvt, QK_PLANE,
                                                 Dq, Dq, Dq, Sq, oa, ob, oc, 0.25f, nullptr, 2, 0);
    }

    // 3) scores (fp32) = q_s.k_s / 16, single hi-pass
    {
        dim3 grid(Sq / 128, Sq / 128, Bq * Hq);
        Off oa = { 1, SDc, 1, 0 };
        Off ob = { 1, SDc, 1, 0 };
        Off oc = { 1, SSc, 1, 0 };
        gemm_mma<0><<<grid, GTHREADS, SMEM_SZ>>>(pqs, QK_PLANE, pks, QK_PLANE, pattn, 0,
                                                 Dq, Dq, Dq, Sq, oa, ob, oc, 1.0f / 16.0f, nullptr, 0, 0);
    }

    // 4) row stats + head-average (no prob materialization)
    stats_avg_kernel<<<Bq * Sq, 256, 65536>>>(attn_avg);

    // 5) PV with on-the-fly softmax probs
    pv_kernel<<<dim3(2, 32, Bq * Hq), 512, PV_SMEM>>>(pattn, pvt, pzs);

    // 6) out = (z_s . wz_s)/2048 + bz; keep Zh.Wz_lo (PMASK=1)
    {
        dim3 grid(Dq / 128, (Bq * Sq) / 128, 1);
        Off oz = { 1, 0, 1, 0 };
        gemm_mma<1><<<grid, GTHREADS, SMEM_SZ>>>(pzs, Z_PLANE, pwz, W_PLANE, out, 0,
                                                 Hq * Dq, Hq * Dq, Hq * Dq, Dq,
                                                 oz, oz, oz, 1.0f / 2048.0f, bz, 0, 0);
    }
}

// round 13
// speedup vs baseline: 1.0462x; 1.0462x over previous
#include <cuda_runtime.h>
#include <cuda_fp16.h>
#include <math.h>
#include <stdint.h>

#define Bq 2
#define Sq 2048
#define Dq 512
#define Hq 8

#define SDc  ((long)Sq * Dq)
#define SSc  ((long)Sq * Sq)
#define DDc  ((long)Dq * Dq)

#define X_PLANE    ((long)Bq * Sq * Dq)
#define W_PLANE    ((long)Hq * Dq * Dq)
#define QK_PLANE   ((long)Bq * Hq * Sq * Dq)
#define Z_PLANE    QK_PLANE

__device__ __align__(256) float g_attn[(long)Bq * Hq * Sq * Sq];
__device__ __align__(256) __half g_xq [X_PLANE];
__device__ __align__(256) __half g_xk [X_PLANE];
__device__ __align__(256) __half g_xv [X_PLANE];
__device__ __align__(256) __half g_wqt[W_PLANE];
__device__ __align__(256) __half g_wkt[W_PLANE];
__device__ __align__(256) __half g_wvt[W_PLANE];
__device__ __align__(256) __half g_wzt[2 * W_PLANE];    // hi + lo
__device__ __align__(256) __half g_qs [QK_PLANE];
__device__ __align__(256) __half g_ks [QK_PLANE];
__device__ __align__(256) __half g_vts[QK_PLANE];       // [b,h,e,s] hi
__device__ __align__(256) __half g_zs [Z_PLANE];        // [b,s,h*D] hi
__device__ __align__(256) float g_m [(long)Bq * Hq * Sq];
__device__ __align__(256) float g_ti[(long)Bq * Hq * Sq];

struct Off { int dv; long s1; int md; long s2; };

__device__ __forceinline__ uint32_t smem_u32(const void* p) {
    uint32_t a;
    asm("{ .reg .u64 t; cvta.to.shared.u64 t, %1; cvt.u32.u64 %0, t; }" : "=r"(a) : "l"(p));
    return a;
}
__device__ __forceinline__ void cpasync16(uint32_t dst, const void* src) {
    asm volatile("cp.async.cg.shared.global [%0], [%1], 16;" :: "r"(dst), "l"(src) : "memory");
}
#define CP_COMMIT() asm volatile("cp.async.commit_group;" ::: "memory")
#define CP_WAIT1()  asm volatile("cp.async.wait_group 1;" ::: "memory")
#define CP_WAIT0()  asm volatile("cp.async.wait_group 0;" ::: "memory")

#define LDSM4(r, a) \
    asm volatile("ldmatrix.sync.aligned.m8n8.x4.shared.b16 {%0,%1,%2,%3}, [%4];" \
        : "=r"((r)[0]), "=r"((r)[1]), "=r"((r)[2]), "=r"((r)[3]) : "r"(a))

#define MMAF(c, a, b0, b1) \
    asm volatile("mma.sync.aligned.m16n8k16.row.col.f32.f16.f16.f32 " \
        "{%0,%1,%2,%3},{%4,%5,%6,%7},{%8,%9},{%0,%1,%2,%3};" \
        : "+f"((c)[0]), "+f"((c)[1]), "+f"((c)[2]), "+f"((c)[3]) \
        : "r"((a)[0]), "r"((a)[1]), "r"((a)[2]), "r"((a)[3]), "r"(b0), "r"(b1))

#define MMAH(c, a, b0, b1) \
    asm volatile("mma.sync.aligned.m16n8k16.row.col.f16.f16.f16.f16 " \
        "{%0,%1},{%2,%3,%4,%5},{%6,%7},{%0,%1};" \
        : "+r"((c)[0]), "+r"((c)[1]) \
        : "r"((a)[0]), "r"((a)[1]), "r"((a)[2]), "r"((a)[3]), "r"(b0), "r"(b1))

__device__ __forceinline__ void split1(float x, __half& h, __half& l) {
    h = __float2half_rn(x);
    l = __float2half_rn(x - __half2float(h));
}
__device__ __forceinline__ uint32_t pack2(__half a, __half b) {
    __half2 t; t.x = a; t.y = b;
    return *reinterpret_cast<uint32_t*>(&t);
}
__device__ __forceinline__ void sts8(uint32_t addr, uint32_t x, uint32_t y) {
    asm volatile("st.shared.v2.b32 [%0], {%1,%2};" :: "r"(addr), "r"(x), "r"(y) : "memory");
}

#define STAGE_B  16384
#define STAGE_SZ 32768
#define NSTAGE   3
#define SMEM_SZ  (NSTAGE * STAGE_SZ)
#define GTHREADS 512

// ---------------------------------------------------------------------------
// fp16 HMMA TN GEMM (R11 design). PMASK: 0 = hi-pass only; 1 adds Ah.Bl f16acc.
// mode 0: fp32 out (+bias). mode 1: fp16 hi out. mode 2: fp16 hi transposed.
// ---------------------------------------------------------------------------
template <int PMASK>
__global__ void __launch_bounds__(GTHREADS, 1)
gemm_mma(const __half* __restrict__ A, long aplane,
         const __half* __restrict__ B, long bplane,
         void* Cv,
         int K, int lda, int ldb, int ldc,
         Off oa, Off ob, Off oc,
         float alpha, const float* __restrict__ bias, int mode)
{
    constexpr bool needBlo = (PMASK & 1) != 0;

    extern __shared__ char smem[];
    const uint32_t sm = smem_u32(smem);
    const int tid = threadIdx.x, wid = tid >> 5, lane = tid & 31;
    const int z = blockIdx.z;

    const __half* Ahp = A + (long)(z / oa.dv) * oa.s1 + (long)(z % oa.md) * oa.s2;
    const __half* Bhp = B + (long)(z / ob.dv) * ob.s1 + (long)(z % ob.md) * ob.s2;
    const long coff = (long)(z / oc.dv) * oc.s1 + (long)(z % oc.md) * oc.s2;

    const long row0 = (long)blockIdx.y * 128;
    const long col0 = (long)blockIdx.x * 128;

    const int lrow = tid >> 2;
    const int c0   = (tid & 3) * 2;
    const int lpl  = c0 >> 2;
    const __half* Asrc = Ahp + (row0 + lrow) * lda + (c0 & 3) * 8;  // hi only
    const __half* Bsrc = (lpl ? Bhp + bplane : Bhp) + (col0 + lrow) * ldb + (c0 & 3) * 8;
    const bool doA = (lpl == 0);
    const bool doB = (lpl == 0) || needBlo;
    uint32_t soff[2];
    #pragma unroll
    for (int j = 0; j < 2; ++j)
        soff[j] = lrow * 128 + (((c0 + j) ^ (lrow & 7)) << 4);

    const int wm = wid & 3, wn = wid >> 2;
    const int g = lane >> 3, r8 = lane & 7;
    const int a_roff = ((g & 1) << 3) + r8;
    const int a_kh   = g >> 1;
    const int b_roff = ((g >> 1) << 3) + r8;
    const int b_kh   = g & 1;

    uint32_t a_row[2], a_rx[2];
    #pragma unroll
    for (int mt = 0; mt < 2; ++mt) {
        const int row = wm * 32 + mt * 16 + a_roff;
        a_row[mt] = row * 128;
        a_rx[mt] = row & 7;
    }
    uint32_t b_row[2], b_rx[2];
    #pragma unroll
    for (int np = 0; np < 2; ++np) {
        const int row = wn * 32 + np * 16 + b_roff;
        b_row[np] = row * 128;
        b_rx[np] = row & 7;
    }

    float acc[2][4][4];
    uint32_t acch[2][4][2];
    #pragma unroll
    for (int i = 0; i < 2; ++i)
        #pragma unroll
        for (int j = 0; j < 4; ++j) {
            #pragma unroll
            for (int q = 0; q < 4; ++q) acc[i][j][q] = 0.0f;
            acch[i][j][0] = 0u; acch[i][j][1] = 0u;
        }

    const int nst = K / 32;

    #pragma unroll
    for (int p = 0; p < 2; ++p) {
        if (p < nst) {
            const uint32_t tb = sm + p * STAGE_SZ;
            const long k0 = (long)p * 32;
            #pragma unroll
            for (int j = 0; j < 2; ++j) {
                if (doA) cpasync16(tb + soff[j], Asrc + k0 + j * 8);
                if (doB) cpasync16(tb + STAGE_B + soff[j], Bsrc + k0 + j * 8);
            }
        }
        CP_COMMIT();
    }

    int stg = 0;
    for (int s = 0; s < nst; ++s) {
        if (s + 1 < nst) CP_WAIT1(); else CP_WAIT0();
        __syncthreads();

        const uint32_t tb = sm + stg * STAGE_SZ;
        const uint32_t tba = tb, tbb = tb + STAGE_B;

        #pragma unroll
        for (int ks = 0; ks < 2; ++ks) {
            const int ca = ks * 2 + a_kh;
            const int cb = ks * 2 + b_kh;

            uint32_t Ahr[2][4], Bhr[2][4];
            #pragma unroll
            for (int mt = 0; mt < 2; ++mt)
                LDSM4(Ahr[mt], tba + a_row[mt] + ((ca ^ a_rx[mt]) << 4));
            #pragma unroll
            for (int np = 0; np < 2; ++np)
                LDSM4(Bhr[np], tbb + b_row[np] + ((cb ^ b_rx[np]) << 4));
            #pragma unroll
            for (int mt = 0; mt < 2; ++mt)
                #pragma unroll
                for (int nt = 0; nt < 4; ++nt) {
                    const int np = nt >> 1, s2 = (nt & 1) * 2;
                    MMAF(acc[mt][nt], Ahr[mt], Bhr[np][s2], Bhr[np][s2 + 1]);
                }

            if (needBlo) {
                uint32_t Blr[2][4];
                #pragma unroll
                for (int np = 0; np < 2; ++np)
                    LDSM4(Blr[np], tbb + b_row[np] + (((cb + 4) ^ b_rx[np]) << 4));
                #pragma unroll
                for (int mt = 0; mt < 2; ++mt)
                    #pragma unroll
                    for (int nt = 0; nt < 4; ++nt) {
                        const int np = nt >> 1, s2 = (nt & 1) * 2;
                        MMAH(acch[mt][nt], Ahr[mt], Blr[np][s2], Blr[np][s2 + 1]);
                    }
            }
        }

        if (s + 2 < nst) {
            int ps = stg + 2; if (ps >= NSTAGE) ps -= NSTAGE;
            const uint32_t pb = sm + ps * STAGE_SZ;
            const long k0 = (long)(s + 2) * 32;
            #pragma unroll
            for (int j = 0; j < 2; ++j) {
                if (doA) cpasync16(pb + soff[j], Asrc + k0 + j * 8);
                if (doB) cpasync16(pb + STAGE_B + soff[j], Bsrc + k0 + j * 8);
            }
        }
        CP_COMMIT();

        if (++stg == NSTAGE) stg = 0;
    }

    const int r_in = lane >> 2, c_in = (lane & 3) * 2;
    #pragma unroll
    for (int mt = 0; mt < 2; ++mt) {
        #pragma unroll
        for (int half = 0; half < 2; ++half) {
            const long row = row0 + wm * 32 + mt * 16 + half * 8 + r_in;
            #pragma unroll
            for (int nt = 0; nt < 4; ++nt) {
                const int colg = (int)col0 + wn * 32 + nt * 8 + c_in;
                float v0 = acc[mt][nt][half * 2 + 0];
                float v1 = acc[mt][nt][half * 2 + 1];
                if (PMASK) {
                    float2 cf = __half22float2(*reinterpret_cast<__half2*>(&acch[mt][nt][half]));
                    v0 += cf.x;
                    v1 += cf.y;
                }
                v0 *= alpha;
                v1 *= alpha;
                if (mode == 0) {
                    if (bias) { v0 += bias[colg]; v1 += bias[colg + 1]; }
                    *(float2*)((float*)Cv + coff + row * ldc + colg) = make_float2(v0, v1);
                } else if (mode == 1) {
                    uint32_t hw = pack2(__float2half_rn(v0), __float2half_rn(v1));
                    *(uint32_t*)((__half*)Cv + coff + row * ldc + colg) = hw;
                } else {
                    __half* Ch = (__half*)Cv + coff;
                    Ch[(long)colg * ldc + row] = __float2half_rn(v0);
                    Ch[(long)(colg + 1) * ldc + row] = __float2half_rn(v1);
                }
            }
        }
    }
}

// ---------------------------------------------------------------------------
// PV kernel (R12): probs computed on the fly from fp32 scores + (m, 1024/t).
// Block tile 64x256, K-chunk 32, 16 warps, 3-stage pipeline.
// Passes: P_hi.V_hi (f32acc) + P_lo.V_hi (f16acc). Output z_s hi to g_zs.
// ---------------------------------------------------------------------------
#define PV_BB   8192
#define PV_STG  40960
#define PV_SMEM (3 * PV_STG)

__global__ void __launch_bounds__(512, 1)
pv_kernel(const float* __restrict__ S, const __half* __restrict__ V,
          __half* __restrict__ Z)
{
    extern __shared__ char smem[];
    const uint32_t sm = smem_u32(smem);
    const int tid = threadIdx.x, wid = tid >> 5, lane = tid & 31;
    const int z = blockIdx.z;
    const long row0 = (long)blockIdx.y * 64;
    const long col0 = (long)blockIdx.x * 256;

    const int ar  = tid >> 3;
    const int seg = tid & 7;
    const long rowg = row0 + ar;
    const float* Sp = S + (long)z * SSc + rowg * Sq + seg * 4;
    const float m  = g_m [(long)z * Sq + rowg];
    const float ti = g_ti[(long)z * Sq + rowg];
    const uint32_t a_hi = ar * 128 + ((((seg >> 1) + 0) ^ (ar & 7)) << 4) + (seg & 1) * 8;
    const uint32_t a_lo = ar * 128 + ((((seg >> 1) + 4) ^ (ar & 7)) << 4) + (seg & 1) * 8;

    const int br = tid >> 1;
    const int bc = (tid & 1) * 2;
    const __half* Vp = V + (long)z * SDc + (col0 + br) * Sq;
    const uint32_t b_s0 = br * 128 + (((bc + 0) ^ (br & 7)) << 4);
    const uint32_t b_s1 = br * 128 + (((bc + 1) ^ (br & 7)) << 4);
    const int bko = bc * 8;

    const int wm = wid & 3, wn = wid >> 2;
    const int g = lane >> 3, r8 = lane & 7;
    const int a_roff = ((g & 1) << 3) + r8;
    const int a_kh   = g >> 1;
    const int b_roff = ((g >> 1) << 3) + r8;
    const int b_kh   = g & 1;

    const int arc = wm * 16 + a_roff;
    const uint32_t a_rowb = arc * 128;
    const uint32_t a_rx = arc & 7;
    uint32_t b_rowb[4], b_rx[4];
    #pragma unroll
    for (int np = 0; np < 4; ++np) {
        const int row = wn * 64 + np * 16 + b_roff;
        b_rowb[np] = row * 128;
        b_rx[np] = row & 7;
    }

    float acc[8][4];
    uint32_t acch[8][2];
    #pragma unroll
    for (int j = 0; j < 8; ++j) {
        #pragma unroll
        for (int q = 0; q < 4; ++q) acc[j][q] = 0.0f;
        acch[j][0] = 0u; acch[j][1] = 0u;
    }

    const int nst = Sq / 32;

    #pragma unroll
    for (int p = 0; p < 2; ++p) {
        const uint32_t tb = sm + p * PV_STG;
        const long k0 = (long)p * 32;
        cpasync16(tb + PV_BB + b_s0, Vp + k0 + bko);
        cpasync16(tb + PV_BB + b_s1, Vp + k0 + bko + 8);
        CP_COMMIT();
        float4 sv = *(const float4*)(Sp + k0);
        float p0 = __expf(sv.x - m) * ti, p1 = __expf(sv.y - m) * ti;
        float p2 = __expf(sv.z - m) * ti, p3 = __expf(sv.w - m) * ti;
        __half h0, l0, h1, l1, h2, l2, h3, l3;
        split1(p0, h0, l0); split1(p1, h1, l1);
        split1(p2, h2, l2); split1(p3, h3, l3);
        sts8(tb + a_hi, pack2(h0, h1), pack2(h2, h3));
        sts8(tb + a_lo, pack2(l0, l1), pack2(l2, l3));
    }

    int stg = 0;
    #pragma unroll 1
    for (int s = 0; s < nst; ++s) {
        if (s + 1 < nst) CP_WAIT1(); else CP_WAIT0();
        __syncthreads();

        const bool pf = (s + 2 < nst);
        int ps = stg + 2; if (ps >= NSTAGE) ps -= NSTAGE;
        const uint32_t pb = sm + ps * PV_STG;
        float4 sv;
        if (pf) {
            const long k2 = (long)(s + 2) * 32;
            cpasync16(pb + PV_BB + b_s0, Vp + k2 + bko);
            cpasync16(pb + PV_BB + b_s1, Vp + k2 + bko + 8);
            sv = *(const float4*)(Sp + k2);
        }

        const uint32_t tb = sm + stg * PV_STG;
        #pragma unroll
        for (int ks = 0; ks < 2; ++ks) {
            const int ca = ks * 2 + a_kh;
            const int cb = ks * 2 + b_kh;
            uint32_t Ah[4], Al[4], Bh[4][4];
            LDSM4(Ah, tb + a_rowb + (((ca + 0) ^ a_rx) << 4));
            LDSM4(Al, tb + a_rowb + (((ca + 4) ^ a_rx) << 4));
            #pragma unroll
            for (int np = 0; np < 4; ++np)
                LDSM4(Bh[np], tb + PV_BB + b_rowb[np] + ((cb ^ b_rx[np]) << 4));
            #pragma unroll
            for (int nt = 0; nt < 8; ++nt) {
                const int np = nt >> 1, s2 = (nt & 1) * 2;
                MMAF(acc[nt], Ah, Bh[np][s2], Bh[np][s2 + 1]);
            }
            #pragma unroll
            for (int nt = 0; nt < 8; ++nt) {
                const int np = nt >> 1, s2 = (nt & 1) * 2;
                MMAH(acch[nt], Al, Bh[np][s2], Bh[np][s2 + 1]);
            }
        }

        if (pf) {
            float p0 = __expf(sv.x - m) * ti, p1 = __expf(sv.y - m) * ti;
            float p2 = __expf(sv.z - m) * ti, p3 = __expf(sv.w - m) * ti;
            __half h0, l0, h1, l1, h2, l2, h3, l3;
            split1(p0, h0, l0); split1(p1, h1, l1);
            split1(p2, h2, l2); split1(p3, h3, l3);
            sts8(pb + a_hi, pack2(h0, h1), pack2(h2, h3));
            sts8(pb + a_lo, pack2(l0, l1), pack2(l2, l3));
        }
        CP_COMMIT();

        if (++stg == NSTAGE) stg = 0;
    }

    const int r_in = lane >> 2, c_in = (lane & 3) * 2;
    __half* Zb = Z + (long)(z / Hq) * Sq * (Hq * Dq) + (long)(z % Hq) * Dq;
    #pragma unroll
    for (int half = 0; half < 2; ++half) {
        const long row = row0 + wm * 16 + half * 8 + r_in;
        #pragma unroll
        for (int nt = 0; nt < 8; ++nt) {
            const int colg = (int)col0 + wn * 64 + nt * 8 + c_in;
            float2 cf = __half22float2(*reinterpret_cast<__half2*>(&acch[nt][half]));
            float v0 = (acc[nt][half * 2 + 0] + cf.x) * (1.0f / 128.0f);
            float v1 = (acc[nt][half * 2 + 1] + cf.y) * (1.0f / 128.0f);
            uint32_t hw = pack2(__float2half_rn(v0), __float2half_rn(v1));
            *(uint32_t*)(Zb + row * (Hq * Dq) + colg) = hw;
        }
    }
}

// ---------------------------------------------------------------------------
__global__ void __launch_bounds__(256) cvt_kernel(const float* __restrict__ in,
                                                  __half* __restrict__ hi, float scale)
{
    const long idx = (long)blockIdx.x * 256 + threadIdx.x;
    float4 v = ((const float4*)in)[idx];
    ((uint32_t*)hi)[2 * idx]     = pack2(__float2half_rn(v.x * scale), __float2half_rn(v.y * scale));
    ((uint32_t*)hi)[2 * idx + 1] = pack2(__float2half_rn(v.z * scale), __float2half_rn(v.w * scale));
}

template <bool WLO>
__global__ void __launch_bounds__(256) tsplit_kernel(const float* __restrict__ in,
                                                     __half* __restrict__ outh,
                                                     long plane, int R, int C, float scale)
{
    __shared__ float ts[32][33];
    const int tx = threadIdx.x, ty = threadIdx.y;
    const long zo = (long)blockIdx.z * R * C;
    const int r0 = blockIdx.y * 32, c0 = blockIdx.x * 32;
    #pragma unroll
    for (int i = 0; i < 4; ++i)
        ts[ty + 8 * i][tx] = in[zo + (long)(r0 + ty + 8 * i) * C + c0 + tx];
    __syncthreads();
    #pragma unroll
    for (int i = 0; i < 4; ++i) {
        __half h, l;
        split1(ts[tx][ty + 8 * i] * scale, h, l);
        const long o = zo + (long)(c0 + ty + 8 * i) * R + r0 + tx;
        outh[o] = h;
        if (WLO) outh[o + plane] = l;
    }
}

// ---------------------------------------------------------------------------
// streaming softmax stats + head-average: registers only, no ps write.
// One block per (b, q-row), loops all 8 heads.
// ---------------------------------------------------------------------------
__global__ void __launch_bounds__(256) softmax_stats_kernel(float* __restrict__ avg_out)
{
    const int r = blockIdx.x & (Sq - 1);
    const int b = blockIdx.x >> 11;
    const int tid = threadIdx.x;
    __shared__ float sr[8];

    float avg[8];
    #pragma unroll
    for (int i = 0; i < 8; ++i) avg[i] = 0.0f;

    #pragma unroll 1
    for (int h = 0; h < Hq; ++h) {
        const float* p = g_attn + (((long)b * Hq + h) * Sq + r) * Sq;

        float v[8];
        float mx = -1e30f;
        #pragma unroll
        for (int i = 0; i < 8; ++i) { v[i] = p[tid + i * 256]; mx = fmaxf(mx, v[i]); }
        #pragma unroll
        for (int o = 16; o > 0; o >>= 1) mx = fmaxf(mx, __shfl_xor_sync(~0u, mx, o));
        if ((tid & 31) == 0) sr[tid >> 5] = mx;
        __syncthreads();
        float mm = sr[0];
        #pragma unroll
        for (int i = 1; i < 8; ++i) mm = fmaxf(mm, sr[i]);
        __syncthreads();

        float s = 0.f;
        #pragma unroll
        for (int i = 0; i < 8; ++i) { v[i] = __expf(v[i] - mm); s += v[i]; }
        #pragma unroll
        for (int o = 16; o > 0; o >>= 1) s += __shfl_xor_sync(~0u, s, o);
        if ((tid & 31) == 0) sr[tid >> 5] = s;
        __syncthreads();
        float t = 0.f;
        #pragma unroll
        for (int i = 0; i < 8; ++i) t += sr[i];
        __syncthreads();

        const float inv = 1.0f / t;
        #pragma unroll
        for (int i = 0; i < 8; ++i) avg[i] += v[i] * inv;

        if (tid == 0) {
            g_m [((long)b * Hq + h) * Sq + r] = mm;
            g_ti[((long)b * Hq + h) * Sq + r] = 1024.0f / t;
        }
    }

    float* dst = avg_out + ((long)b * Sq + r) * Sq;
    #pragma unroll
    for (int i = 0; i < 8; ++i)
        dst[tid + i * 256] = avg[i] * 0.125f;
}

// ---------------------------------------------------------------------------
extern "C" void kernel_launch(void* const* d_in, const int* in_sizes, int n_in,
                              void* d_out, int out_size)
{
    (void)in_sizes; (void)n_in; (void)out_size;
    const float* Xq = (const float*)d_in[0];
    const float* Xk = (const float*)d_in[1];
    const float* Xv = (const float*)d_in[2];
    const float* Wq = (const float*)d_in[3];
    const float* Wk = (const float*)d_in[4];
    const float* Wv = (const float*)d_in[5];
    const float* Wz = (const float*)d_in[6];
    const float* bz = (const float*)d_in[7];
    float* out = (float*)d_out;
    float* attn_avg = out + (long)Bq * Sq * Dq;

    __half *pxq, *pxk, *pxv, *pwq, *pwk, *pwv, *pwz, *pqs, *pks, *pvt, *pzs;
    float* pattn;
    cudaGetSymbolAddress((void**)&pxq, g_xq);
    cudaGetSymbolAddress((void**)&pxk, g_xk);
    cudaGetSymbolAddress((void**)&pxv, g_xv);
    cudaGetSymbolAddress((void**)&pwq, g_wqt);
    cudaGetSymbolAddress((void**)&pwk, g_wkt);
    cudaGetSymbolAddress((void**)&pwv, g_wvt);
    cudaGetSymbolAddress((void**)&pwz, g_wzt);
    cudaGetSymbolAddress((void**)&pqs, g_qs);
    cudaGetSymbolAddress((void**)&pks, g_ks);
    cudaGetSymbolAddress((void**)&pvt, g_vts);
    cudaGetSymbolAddress((void**)&pzs, g_zs);
    cudaGetSymbolAddress((void**)&pattn, g_attn);

    cudaFuncSetAttribute(gemm_mma<0>, cudaFuncAttributeMaxDynamicSharedMemorySize, SMEM_SZ);
    cudaFuncSetAttribute(gemm_mma<1>, cudaFuncAttributeMaxDynamicSharedMemorySize, SMEM_SZ);
    cudaFuncSetAttribute(pv_kernel, cudaFuncAttributeMaxDynamicSharedMemorySize, PV_SMEM);

    const float inv4 = (float)(1.0 / pow((double)Dq, 0.25));

    // 1) convert inputs/weights to fp16 (hi only; Wz keeps lo)
    {
        int nb = (int)(X_PLANE / 1024);
        cvt_kernel<<<nb, 256>>>(Xq, pxq, 1.0f);
        cvt_kernel<<<nb, 256>>>(Xk, pxk, 1.0f);
        cvt_kernel<<<nb, 256>>>(Xv, pxv, 1.0f);
        dim3 tb(32, 8);
        tsplit_kernel<false><<<dim3(16, 16, 8), tb>>>(Wq, pwq, W_PLANE, Dq, Dq, 16.0f);
        tsplit_kernel<false><<<dim3(16, 16, 8), tb>>>(Wk, pwk, W_PLANE, Dq, Dq, 16.0f);
        tsplit_kernel<false><<<dim3(16, 16, 8), tb>>>(Wv, pwv, W_PLANE, Dq, Dq, 16.0f);
        tsplit_kernel<true><<<dim3(16, 128, 1), tb>>>(Wz, pwz, W_PLANE, Hq * Dq, Dq, 64.0f);
    }

    // 2) projections (TN), single hi-pass. q_s/k_s = 4x true, v_s = 4x v.
    {
        dim3 grid(Dq / 128, Sq / 128, Bq * Hq);
        Off oa = { Hq, SDc, 1, 0 };
        Off ob = { 1, 0, Hq, DDc };
        Off oc = { 1, SDc, 1, 0 };
        gemm_mma<0><<<grid, GTHREADS, SMEM_SZ>>>(pxq, 0, pwq, 0, pqs,
                                                 Dq, Dq, Dq, Dq, oa, ob, oc, inv4 * 0.25f, nullptr, 1);
        gemm_mma<0><<<grid, GTHREADS, SMEM_SZ>>>(pxk, 0, pwk, 0, pks,
                                                 Dq, Dq, Dq, Dq, oa, ob, oc, inv4 * 0.25f, nullptr, 1);
        gemm_mma<0><<<grid, GTHREADS, SMEM_SZ>>>(pxv, 0, pwv, 0, pvt,
                                                 Dq, Dq, Dq, Sq, oa, ob, oc, 0.25f, nullptr, 2);
    }

    // 3) scores (fp32) = q_s.k_s / 16
    {
        dim3 grid(Sq / 128, Sq / 128, Bq * Hq);
        Off oa = { 1, SDc, 1, 0 };
        Off ob = { 1, SDc, 1, 0 };
        Off oc = { 1, SSc, 1, 0 };
        gemm_mma<0><<<grid, GTHREADS, SMEM_SZ>>>(pqs, 0, pks, 0, pattn,
                                                 Dq, Dq, Dq, Sq, oa, ob, oc, 1.0f / 16.0f, nullptr, 0);
    }

    // 4) streaming softmax stats + head-average
    softmax_stats_kernel<<<Bq * Sq, 256>>>(attn_avg);

    // 5) PV with on-the-fly softmax probs
    pv_kernel<<<dim3(2, 32, Bq * Hq), 512, PV_SMEM>>>(pattn, pvt, pzs);

    // 6) out = (z_s . wz_s)/2048 + bz (hi + Zh.Wz_lo correction)
    {
        dim3 grid(Dq / 128, (Bq * Sq) / 128, 1);
        Off oz = { 1, 0, 1, 0 };
        gemm_mma<1><<<grid, GTHREADS, SMEM_SZ>>>(pzs, 0, pwz, W_PLANE, out,
                                                 Hq * Dq, Hq * Dq, Hq * Dq, Dq,
                                                 oz, oz, oz, 1.0f / 2048.0f, bz, 0);
    }
}

// round 14
// speedup vs baseline: 1.0528x; 1.0062x over previous
#include <cuda_runtime.h>
#include <cuda_fp16.h>
#include <math.h>
#include <stdint.h>

#define Bq 2
#define Sq 2048
#define Dq 512
#define Hq 8

#define SDc  ((long)Sq * Dq)
#define SSc  ((long)Sq * Sq)
#define DDc  ((long)Dq * Dq)

#define X_PLANE    ((long)Bq * Sq * Dq)
#define W_PLANE    ((long)Hq * Dq * Dq)
#define QK_PLANE   ((long)Bq * Hq * Sq * Dq)
#define Z_PLANE    QK_PLANE

__device__ __align__(256) float g_attn[(long)Bq * Hq * Sq * Sq];
__device__ __align__(256) __half g_x  [3 * X_PLANE];     // xq | xk | xv
__device__ __align__(256) __half g_w  [3 * W_PLANE];     // wq | wk | wv (transposed)
__device__ __align__(256) __half g_wzt[2 * W_PLANE];     // wz hi | lo
__device__ __align__(256) __half g_qk [2 * QK_PLANE];    // q_s | k_s
__device__ __align__(256) __half g_vts[QK_PLANE];        // [b,h,e,s]
__device__ __align__(256) __half g_zs [Z_PLANE];         // [b,s,h*D]
__device__ __align__(256) float g_m [(long)Bq * Hq * Sq];
__device__ __align__(256) float g_ti[(long)Bq * Hq * Sq];

struct Off { int dv; long s1; int md; long s2; };

__device__ __forceinline__ uint32_t smem_u32(const void* p) {
    uint32_t a;
    asm("{ .reg .u64 t; cvta.to.shared.u64 t, %1; cvt.u32.u64 %0, t; }" : "=r"(a) : "l"(p));
    return a;
}
__device__ __forceinline__ void cpasync16(uint32_t dst, const void* src) {
    asm volatile("cp.async.cg.shared.global [%0], [%1], 16;" :: "r"(dst), "l"(src) : "memory");
}
#define CP_COMMIT() asm volatile("cp.async.commit_group;" ::: "memory")
#define CP_WAIT1()  asm volatile("cp.async.wait_group 1;" ::: "memory")
#define CP_WAIT0()  asm volatile("cp.async.wait_group 0;" ::: "memory")

#define LDSM4(r, a) \
    asm volatile("ldmatrix.sync.aligned.m8n8.x4.shared.b16 {%0,%1,%2,%3}, [%4];" \
        : "=r"((r)[0]), "=r"((r)[1]), "=r"((r)[2]), "=r"((r)[3]) : "r"(a))

#define MMAF(c, a, b0, b1) \
    asm volatile("mma.sync.aligned.m16n8k16.row.col.f32.f16.f16.f32 " \
        "{%0,%1,%2,%3},{%4,%5,%6,%7},{%8,%9},{%0,%1,%2,%3};" \
        : "+f"((c)[0]), "+f"((c)[1]), "+f"((c)[2]), "+f"((c)[3]) \
        : "r"((a)[0]), "r"((a)[1]), "r"((a)[2]), "r"((a)[3]), "r"(b0), "r"(b1))

#define MMAH(c, a, b0, b1) \
    asm volatile("mma.sync.aligned.m16n8k16.row.col.f16.f16.f16.f16 " \
        "{%0,%1},{%2,%3,%4,%5},{%6,%7},{%0,%1};" \
        : "+r"((c)[0]), "+r"((c)[1]) \
        : "r"((a)[0]), "r"((a)[1]), "r"((a)[2]), "r"((a)[3]), "r"(b0), "r"(b1))

__device__ __forceinline__ void split1(float x, __half& h, __half& l) {
    h = __float2half_rn(x);
    l = __float2half_rn(x - __half2float(h));
}
__device__ __forceinline__ uint32_t pack2(__half a, __half b) {
    __half2 t; t.x = a; t.y = b;
    return *reinterpret_cast<uint32_t*>(&t);
}
__device__ __forceinline__ void sts8(uint32_t addr, uint32_t x, uint32_t y) {
    asm volatile("st.shared.v2.b32 [%0], {%1,%2};" :: "r"(addr), "r"(x), "r"(y) : "memory");
}

#define STAGE_B  16384
#define STAGE_SZ 32768
#define NSTAGE   3
#define SMEM_SZ  (NSTAGE * STAGE_SZ)
#define GTHREADS 512

// ---------------------------------------------------------------------------
// fp16 HMMA TN GEMM. PMASK: 0 = hi-pass only; 1 adds Ah.Bl f16acc.
// mode 0: fp32 out (+bias). mode 1: fp16 hi out. mode 2: fp16 hi transposed.
// ---------------------------------------------------------------------------
template <int PMASK>
__global__ void __launch_bounds__(GTHREADS, 1)
gemm_mma(const __half* __restrict__ A, long aplane,
         const __half* __restrict__ B, long bplane,
         void* Cv,
         int K, int lda, int ldb, int ldc,
         Off oa, Off ob, Off oc,
         float alpha, const float* __restrict__ bias, int mode)
{
    constexpr bool needBlo = (PMASK & 1) != 0;

    extern __shared__ char smem[];
    const uint32_t sm = smem_u32(smem);
    const int tid = threadIdx.x, wid = tid >> 5, lane = tid & 31;
    const int z = blockIdx.z;

    const __half* Ahp = A + (long)(z / oa.dv) * oa.s1 + (long)(z % oa.md) * oa.s2;
    const __half* Bhp = B + (long)(z / ob.dv) * ob.s1 + (long)(z % ob.md) * ob.s2;
    const long coff = (long)(z / oc.dv) * oc.s1 + (long)(z % oc.md) * oc.s2;

    const long row0 = (long)blockIdx.y * 128;
    const long col0 = (long)blockIdx.x * 128;

    const int lrow = tid >> 2;
    const int c0   = (tid & 3) * 2;
    const int lpl  = c0 >> 2;
    const __half* Asrc = Ahp + (row0 + lrow) * lda + (c0 & 3) * 8;
    const __half* Bsrc = (lpl ? Bhp + bplane : Bhp) + (col0 + lrow) * ldb + (c0 & 3) * 8;
    const bool doA = (lpl == 0);
    const bool doB = (lpl == 0) || needBlo;
    uint32_t soff[2];
    #pragma unroll
    for (int j = 0; j < 2; ++j)
        soff[j] = lrow * 128 + (((c0 + j) ^ (lrow & 7)) << 4);

    const int wm = wid & 3, wn = wid >> 2;
    const int g = lane >> 3, r8 = lane & 7;
    const int a_roff = ((g & 1) << 3) + r8;
    const int a_kh   = g >> 1;
    const int b_roff = ((g >> 1) << 3) + r8;
    const int b_kh   = g & 1;

    uint32_t a_row[2], a_rx[2];
    #pragma unroll
    for (int mt = 0; mt < 2; ++mt) {
        const int row = wm * 32 + mt * 16 + a_roff;
        a_row[mt] = row * 128;
        a_rx[mt] = row & 7;
    }
    uint32_t b_row[2], b_rx[2];
    #pragma unroll
    for (int np = 0; np < 2; ++np) {
        const int row = wn * 32 + np * 16 + b_roff;
        b_row[np] = row * 128;
        b_rx[np] = row & 7;
    }

    float acc[2][4][4];
    uint32_t acch[2][4][2];
    #pragma unroll
    for (int i = 0; i < 2; ++i)
        #pragma unroll
        for (int j = 0; j < 4; ++j) {
            #pragma unroll
            for (int q = 0; q < 4; ++q) acc[i][j][q] = 0.0f;
            acch[i][j][0] = 0u; acch[i][j][1] = 0u;
        }

    const int nst = K / 32;

    #pragma unroll
    for (int p = 0; p < 2; ++p) {
        if (p < nst) {
            const uint32_t tb = sm + p * STAGE_SZ;
            const long k0 = (long)p * 32;
            #pragma unroll
            for (int j = 0; j < 2; ++j) {
                if (doA) cpasync16(tb + soff[j], Asrc + k0 + j * 8);
                if (doB) cpasync16(tb + STAGE_B + soff[j], Bsrc + k0 + j * 8);
            }
        }
        CP_COMMIT();
    }

    int stg = 0;
    for (int s = 0; s < nst; ++s) {
        if (s + 1 < nst) CP_WAIT1(); else CP_WAIT0();
        __syncthreads();

        const uint32_t tb = sm + stg * STAGE_SZ;
        const uint32_t tba = tb, tbb = tb + STAGE_B;

        #pragma unroll
        for (int ks = 0; ks < 2; ++ks) {
            const int ca = ks * 2 + a_kh;
            const int cb = ks * 2 + b_kh;

            uint32_t Ahr[2][4], Bhr[2][4];
            #pragma unroll
            for (int mt = 0; mt < 2; ++mt)
                LDSM4(Ahr[mt], tba + a_row[mt] + ((ca ^ a_rx[mt]) << 4));
            #pragma unroll
            for (int np = 0; np < 2; ++np)
                LDSM4(Bhr[np], tbb + b_row[np] + ((cb ^ b_rx[np]) << 4));
            #pragma unroll
            for (int mt = 0; mt < 2; ++mt)
                #pragma unroll
                for (int nt = 0; nt < 4; ++nt) {
                    const int np = nt >> 1, s2 = (nt & 1) * 2;
                    MMAF(acc[mt][nt], Ahr[mt], Bhr[np][s2], Bhr[np][s2 + 1]);
                }

            if (needBlo) {
                uint32_t Blr[2][4];
                #pragma unroll
                for (int np = 0; np < 2; ++np)
                    LDSM4(Blr[np], tbb + b_row[np] + (((cb + 4) ^ b_rx[np]) << 4));
                #pragma unroll
                for (int mt = 0; mt < 2; ++mt)
                    #pragma unroll
                    for (int nt = 0; nt < 4; ++nt) {
                        const int np = nt >> 1, s2 = (nt & 1) * 2;
                        MMAH(acch[mt][nt], Ahr[mt], Blr[np][s2], Blr[np][s2 + 1]);
                    }
            }
        }

        if (s + 2 < nst) {
            int ps = stg + 2; if (ps >= NSTAGE) ps -= NSTAGE;
            const uint32_t pb = sm + ps * STAGE_SZ;
            const long k0 = (long)(s + 2) * 32;
            #pragma unroll
            for (int j = 0; j < 2; ++j) {
                if (doA) cpasync16(pb + soff[j], Asrc + k0 + j * 8);
                if (doB) cpasync16(pb + STAGE_B + soff[j], Bsrc + k0 + j * 8);
            }
        }
        CP_COMMIT();

        if (++stg == NSTAGE) stg = 0;
    }

    const int r_in = lane >> 2, c_in = (lane & 3) * 2;
    #pragma unroll
    for (int mt = 0; mt < 2; ++mt) {
        #pragma unroll
        for (int half = 0; half < 2; ++half) {
            const long row = row0 + wm * 32 + mt * 16 + half * 8 + r_in;
            #pragma unroll
            for (int nt = 0; nt < 4; ++nt) {
                const int colg = (int)col0 + wn * 32 + nt * 8 + c_in;
                float v0 = acc[mt][nt][half * 2 + 0];
                float v1 = acc[mt][nt][half * 2 + 1];
                if (PMASK) {
                    float2 cf = __half22float2(*reinterpret_cast<__half2*>(&acch[mt][nt][half]));
                    v0 += cf.x;
                    v1 += cf.y;
                }
                v0 *= alpha;
                v1 *= alpha;
                if (mode == 0) {
                    if (bias) { v0 += bias[colg]; v1 += bias[colg + 1]; }
                    *(float2*)((float*)Cv + coff + row * ldc + colg) = make_float2(v0, v1);
                } else if (mode == 1) {
                    uint32_t hw = pack2(__float2half_rn(v0), __float2half_rn(v1));
                    *(uint32_t*)((__half*)Cv + coff + row * ldc + colg) = hw;
                } else {
                    __half* Ch = (__half*)Cv + coff;
                    Ch[(long)colg * ldc + row] = __float2half_rn(v0);
                    Ch[(long)(colg + 1) * ldc + row] = __float2half_rn(v1);
                }
            }
        }
    }
}

// ---------------------------------------------------------------------------
// PV kernel: probs on the fly from fp32 scores + (m, 1024/t). 64x256 tile.
// ---------------------------------------------------------------------------
#define PV_BB   8192
#define PV_STG  40960
#define PV_SMEM (3 * PV_STG)

__global__ void __launch_bounds__(512, 1)
pv_kernel(const float* __restrict__ S, const __half* __restrict__ V,
          __half* __restrict__ Z)
{
    extern __shared__ char smem[];
    const uint32_t sm = smem_u32(smem);
    const int tid = threadIdx.x, wid = tid >> 5, lane = tid & 31;
    const int z = blockIdx.z;
    const long row0 = (long)blockIdx.y * 64;
    const long col0 = (long)blockIdx.x * 256;

    const int ar  = tid >> 3;
    const int seg = tid & 7;
    const long rowg = row0 + ar;
    const float* Sp = S + (long)z * SSc + rowg * Sq + seg * 4;
    const float m  = g_m [(long)z * Sq + rowg];
    const float ti = g_ti[(long)z * Sq + rowg];
    const uint32_t a_hi = ar * 128 + ((((seg >> 1) + 0) ^ (ar & 7)) << 4) + (seg & 1) * 8;
    const uint32_t a_lo = ar * 128 + ((((seg >> 1) + 4) ^ (ar & 7)) << 4) + (seg & 1) * 8;

    const int br = tid >> 1;
    const int bc = (tid & 1) * 2;
    const __half* Vp = V + (long)z * SDc + (col0 + br) * Sq;
    const uint32_t b_s0 = br * 128 + (((bc + 0) ^ (br & 7)) << 4);
    const uint32_t b_s1 = br * 128 + (((bc + 1) ^ (br & 7)) << 4);
    const int bko = bc * 8;

    const int wm = wid & 3, wn = wid >> 2;
    const int g = lane >> 3, r8 = lane & 7;
    const int a_roff = ((g & 1) << 3) + r8;
    const int a_kh   = g >> 1;
    const int b_roff = ((g >> 1) << 3) + r8;
    const int b_kh   = g & 1;

    const int arc = wm * 16 + a_roff;
    const uint32_t a_rowb = arc * 128;
    const uint32_t a_rx = arc & 7;
    uint32_t b_rowb[4], b_rx[4];
    #pragma unroll
    for (int np = 0; np < 4; ++np) {
        const int row = wn * 64 + np * 16 + b_roff;
        b_rowb[np] = row * 128;
        b_rx[np] = row & 7;
    }

    float acc[8][4];
    uint32_t acch[8][2];
    #pragma unroll
    for (int j = 0; j < 8; ++j) {
        #pragma unroll
        for (int q = 0; q < 4; ++q) acc[j][q] = 0.0f;
        acch[j][0] = 0u; acch[j][1] = 0u;
    }

    const int nst = Sq / 32;

    #pragma unroll
    for (int p = 0; p < 2; ++p) {
        const uint32_t tb = sm + p * PV_STG;
        const long k0 = (long)p * 32;
        cpasync16(tb + PV_BB + b_s0, Vp + k0 + bko);
        cpasync16(tb + PV_BB + b_s1, Vp + k0 + bko + 8);
        CP_COMMIT();
        float4 sv = *(const float4*)(Sp + k0);
        float p0 = __expf(sv.x - m) * ti, p1 = __expf(sv.y - m) * ti;
        float p2 = __expf(sv.z - m) * ti, p3 = __expf(sv.w - m) * ti;
        __half h0, l0, h1, l1, h2, l2, h3, l3;
        split1(p0, h0, l0); split1(p1, h1, l1);
        split1(p2, h2, l2); split1(p3, h3, l3);
        sts8(tb + a_hi, pack2(h0, h1), pack2(h2, h3));
        sts8(tb + a_lo, pack2(l0, l1), pack2(l2, l3));
    }

    int stg = 0;
    #pragma unroll 1
    for (int s = 0; s < nst; ++s) {
        if (s + 1 < nst) CP_WAIT1(); else CP_WAIT0();
        __syncthreads();

        const bool pf = (s + 2 < nst);
        int ps = stg + 2; if (ps >= NSTAGE) ps -= NSTAGE;
        const uint32_t pb = sm + ps * PV_STG;
        float4 sv;
        if (pf) {
            const long k2 = (long)(s + 2) * 32;
            cpasync16(pb + PV_BB + b_s0, Vp + k2 + bko);
            cpasync16(pb + PV_BB + b_s1, Vp + k2 + bko + 8);
            sv = *(const float4*)(Sp + k2);
        }

        const uint32_t tb = sm + stg * PV_STG;
        #pragma unroll
        for (int ks = 0; ks < 2; ++ks) {
            const int ca = ks * 2 + a_kh;
            const int cb = ks * 2 + b_kh;
            uint32_t Ah[4], Al[4], Bh[4][4];
            LDSM4(Ah, tb + a_rowb + (((ca + 0) ^ a_rx) << 4));
            LDSM4(Al, tb + a_rowb + (((ca + 4) ^ a_rx) << 4));
            #pragma unroll
            for (int np = 0; np < 4; ++np)
                LDSM4(Bh[np], tb + PV_BB + b_rowb[np] + ((cb ^ b_rx[np]) << 4));
            #pragma unroll
            for (int nt = 0; nt < 8; ++nt) {
                const int np = nt >> 1, s2 = (nt & 1) * 2;
                MMAF(acc[nt], Ah, Bh[np][s2], Bh[np][s2 + 1]);
            }
            #pragma unroll
            for (int nt = 0; nt < 8; ++nt) {
                const int np = nt >> 1, s2 = (nt & 1) * 2;
                MMAH(acch[nt], Al, Bh[np][s2], Bh[np][s2 + 1]);
            }
        }

        if (pf) {
            float p0 = __expf(sv.x - m) * ti, p1 = __expf(sv.y - m) * ti;
            float p2 = __expf(sv.z - m) * ti, p3 = __expf(sv.w - m) * ti;
            __half h0, l0, h1, l1, h2, l2, h3, l3;
            split1(p0, h0, l0); split1(p1, h1, l1);
            split1(p2, h2, l2); split1(p3, h3, l3);
            sts8(pb + a_hi, pack2(h0, h1), pack2(h2, h3));
            sts8(pb + a_lo, pack2(l0, l1), pack2(l2, l3));
        }
        CP_COMMIT();

        if (++stg == NSTAGE) stg = 0;
    }

    const int r_in = lane >> 2, c_in = (lane & 3) * 2;
    __half* Zb = Z + (long)(z / Hq) * Sq * (Hq * Dq) + (long)(z % Hq) * Dq;
    #pragma unroll
    for (int half = 0; half < 2; ++half) {
        const long row = row0 + wm * 16 + half * 8 + r_in;
        #pragma unroll
        for (int nt = 0; nt < 8; ++nt) {
            const int colg = (int)col0 + wn * 64 + nt * 8 + c_in;
            float2 cf = __half22float2(*reinterpret_cast<__half2*>(&acch[nt][half]));
            float v0 = (acc[nt][half * 2 + 0] + cf.x) * (1.0f / 128.0f);
            float v1 = (acc[nt][half * 2 + 1] + cf.y) * (1.0f / 128.0f);
            uint32_t hw = pack2(__float2half_rn(v0), __float2half_rn(v1));
            *(uint32_t*)(Zb + row * (Hq * Dq) + colg) = hw;
        }
    }
}

// ---------------------------------------------------------------------------
// combined fp32->fp16 convert for Xq/Xk/Xv (grid.y selects input)
__global__ void __launch_bounds__(256) cvt3_kernel(const float* __restrict__ a,
                                                   const float* __restrict__ b,
                                                   const float* __restrict__ c,
                                                   __half* __restrict__ dst)
{
    const float* in = (blockIdx.y == 0) ? a : (blockIdx.y == 1) ? b : c;
    __half* out = dst + (long)blockIdx.y * X_PLANE;
    const long idx = (long)blockIdx.x * 256 + threadIdx.x;
    float4 v = ((const float4*)in)[idx];
    ((uint32_t*)out)[2 * idx]     = pack2(__float2half_rn(v.x), __float2half_rn(v.y));
    ((uint32_t*)out)[2 * idx + 1] = pack2(__float2half_rn(v.z), __float2half_rn(v.w));
}

// combined transpose+cvt for Wq/Wk/Wv (z = m*8 + h), scale x16, hi only
__global__ void __launch_bounds__(256) tcvt3_kernel(const float* __restrict__ wq,
                                                    const float* __restrict__ wk,
                                                    const float* __restrict__ wv,
                                                    __half* __restrict__ dst)
{
    __shared__ float ts[32][33];
    const int tx = threadIdx.x, ty = threadIdx.y;
    const int mh = blockIdx.z;
    const int mm = mh >> 3, h = mh & 7;
    const float* in = ((mm == 0) ? wq : (mm == 1) ? wk : wv) + (long)h * DDc;
    __half* out = dst + (long)mm * W_PLANE + (long)h * DDc;
    const int r0 = blockIdx.y * 32, c0 = blockIdx.x * 32;
    #pragma unroll
    for (int i = 0; i < 4; ++i)
        ts[ty + 8 * i][tx] = in[(long)(r0 + ty + 8 * i) * Dq + c0 + tx];
    __syncthreads();
    #pragma unroll
    for (int i = 0; i < 4; ++i)
        out[(long)(c0 + ty + 8 * i) * Dq + r0 + tx] =
            __float2half_rn(ts[tx][ty + 8 * i] * 16.0f);
}

// Wz transpose + split (hi + lo), scale x64
__global__ void __launch_bounds__(256) tsplit_wz_kernel(const float* __restrict__ in,
                                                        __half* __restrict__ outh)
{
    __shared__ float ts[32][33];
    const int tx = threadIdx.x, ty = threadIdx.y;
    const int r0 = blockIdx.y * 32, c0 = blockIdx.x * 32;
    const int R = Hq * Dq, C = Dq;
    #pragma unroll
    for (int i = 0; i < 4; ++i)
        ts[ty + 8 * i][tx] = in[(long)(r0 + ty + 8 * i) * C + c0 + tx];
    __syncthreads();
    #pragma unroll
    for (int i = 0; i < 4; ++i) {
        __half h, l;
        split1(ts[tx][ty + 8 * i] * 64.0f, h, l);
        const long o = (long)(c0 + ty + 8 * i) * R + r0 + tx;
        outh[o] = h;
        outh[o + W_PLANE] = l;
    }
}

// ---------------------------------------------------------------------------
// streaming softmax stats + head-average (R13)
__global__ void __launch_bounds__(256) softmax_stats_kernel(float* __restrict__ avg_out)
{
    const int r = blockIdx.x & (Sq - 1);
    const int b = blockIdx.x >> 11;
    const int tid = threadIdx.x;
    __shared__ float sr[8];

    float avg[8];
    #pragma unroll
    for (int i = 0; i < 8; ++i) avg[i] = 0.0f;

    #pragma unroll 1
    for (int h = 0; h < Hq; ++h) {
        const float* p = g_attn + (((long)b * Hq + h) * Sq + r) * Sq;

        float v[8];
        float mx = -1e30f;
        #pragma unroll
        for (int i = 0; i < 8; ++i) { v[i] = p[tid + i * 256]; mx = fmaxf(mx, v[i]); }
        #pragma unroll
        for (int o = 16; o > 0; o >>= 1) mx = fmaxf(mx, __shfl_xor_sync(~0u, mx, o));
        if ((tid & 31) == 0) sr[tid >> 5] = mx;
        __syncthreads();
        float mm = sr[0];
        #pragma unroll
        for (int i = 1; i < 8; ++i) mm = fmaxf(mm, sr[i]);
        __syncthreads();

        float s = 0.f;
        #pragma unroll
        for (int i = 0; i < 8; ++i) { v[i] = __expf(v[i] - mm); s += v[i]; }
        #pragma unroll
        for (int o = 16; o > 0; o >>= 1) s += __shfl_xor_sync(~0u, s, o);
        if ((tid & 31) == 0) sr[tid >> 5] = s;
        __syncthreads();
        float t = 0.f;
        #pragma unroll
        for (int i = 0; i < 8; ++i) t += sr[i];
        __syncthreads();

        const float inv = 1.0f / t;
        #pragma unroll
        for (int i = 0; i < 8; ++i) avg[i] += v[i] * inv;

        if (tid == 0) {
            g_m [((long)b * Hq + h) * Sq + r] = mm;
            g_ti[((long)b * Hq + h) * Sq + r] = 1024.0f / t;
        }
    }

    float* dst = avg_out + ((long)b * Sq + r) * Sq;
    #pragma unroll
    for (int i = 0; i < 8; ++i)
        dst[tid + i * 256] = avg[i] * 0.125f;
}

// ---------------------------------------------------------------------------
extern "C" void kernel_launch(void* const* d_in, const int* in_sizes, int n_in,
                              void* d_out, int out_size)
{
    (void)in_sizes; (void)n_in; (void)out_size;
    const float* Xq = (const float*)d_in[0];
    const float* Xk = (const float*)d_in[1];
    const float* Xv = (const float*)d_in[2];
    const float* Wq = (const float*)d_in[3];
    const float* Wk = (const float*)d_in[4];
    const float* Wv = (const float*)d_in[5];
    const float* Wz = (const float*)d_in[6];
    const float* bz = (const float*)d_in[7];
    float* out = (float*)d_out;
    float* attn_avg = out + (long)Bq * Sq * Dq;

    __half *px, *pw, *pwz, *pqk, *pvt, *pzs;
    float* pattn;
    cudaGetSymbolAddress((void**)&px, g_x);
    cudaGetSymbolAddress((void**)&pw, g_w);
    cudaGetSymbolAddress((void**)&pwz, g_wzt);
    cudaGetSymbolAddress((void**)&pqk, g_qk);
    cudaGetSymbolAddress((void**)&pvt, g_vts);
    cudaGetSymbolAddress((void**)&pzs, g_zs);
    cudaGetSymbolAddress((void**)&pattn, g_attn);

    cudaFuncSetAttribute(gemm_mma<0>, cudaFuncAttributeMaxDynamicSharedMemorySize, SMEM_SZ);
    cudaFuncSetAttribute(gemm_mma<1>, cudaFuncAttributeMaxDynamicSharedMemorySize, SMEM_SZ);
    cudaFuncSetAttribute(pv_kernel, cudaFuncAttributeMaxDynamicSharedMemorySize, PV_SMEM);

    const float inv4 = (float)(1.0 / pow((double)Dq, 0.25));

    // 1) convert inputs + weights (3 launches)
    cvt3_kernel<<<dim3((int)(X_PLANE / 1024), 3), 256>>>(Xq, Xk, Xv, px);
    {
        dim3 tb(32, 8);
        tcvt3_kernel<<<dim3(16, 16, 24), tb>>>(Wq, Wk, Wv, pw);
        tsplit_wz_kernel<<<dim3(16, 128, 1), tb>>>(Wz, pwz);
    }

    // 2) Q+K projections in ONE launch (z = m*16 + b*8 + h, m in {0,1})
    {
        dim3 grid(Dq / 128, Sq / 128, 32);
        Off oa = { 8, SDc, 1, 0 };                 // (z/8)*SD = (2m+b)*SD
        Off ob = { 16, W_PLANE, 8, DDc };          // m*W_PLANE + h*DD
        Off oc = { 16, QK_PLANE, 16, SDc };        // m*QK_PLANE + (b*8+h)*SD
        gemm_mma<0><<<grid, GTHREADS, SMEM_SZ>>>(px, 0, pw, 0, pqk,
                                                 Dq, Dq, Dq, Dq, oa, ob, oc,
                                                 inv4 * 0.25f, nullptr, 1);
    }
    // V projection (transposed output)
    {
        dim3 grid(Dq / 128, Sq / 128, 16);
        Off oa = { 8, SDc, 1, 0 };
        Off ob = { 1, 0, 8, DDc };
        Off oc = { 1, SDc, 1, 0 };
        gemm_mma<0><<<grid, GTHREADS, SMEM_SZ>>>(px + 2 * X_PLANE, 0, pw + 2 * W_PLANE, 0, pvt,
                                                 Dq, Dq, Dq, Sq, oa, ob, oc,
                                                 0.25f, nullptr, 2);
    }

    // 3) scores (fp32) = q_s.k_s / 16
    {
        dim3 grid(Sq / 128, Sq / 128, Bq * Hq);
        Off oa = { 1, SDc, 1, 0 };
        Off ob = { 1, SDc, 1, 0 };
        Off oc = { 1, SSc, 1, 0 };
        gemm_mma<0><<<grid, GTHREADS, SMEM_SZ>>>(pqk, 0, pqk + QK_PLANE, 0, pattn,
                                                 Dq, Dq, Dq, Sq, oa, ob, oc,
                                                 1.0f / 16.0f, nullptr, 0);
    }

    // 4) streaming softmax stats + head-average
    softmax_stats_kernel<<<Bq * Sq, 256>>>(attn_avg);

    // 5) PV with on-the-fly softmax probs
    pv_kernel<<<dim3(2, 32, Bq * Hq), 512, PV_SMEM>>>(pattn, pvt, pzs);

    // 6) out = (z_s . wz_s)/2048 + bz (hi + Zh.Wz_lo correction)
    {
        dim3 grid(Dq / 128, (Bq * Sq) / 128, 1);
        Off oz = { 1, 0, 1, 0 };
        gemm_mma<1><<<grid, GTHREADS, SMEM_SZ>>>(pzs, 0, pwz, W_PLANE, out,
                                                 Hq * Dq, Hq * Dq, Hq * Dq, Dq,
                                                 oz, oz, oz, 1.0f / 2048.0f, bz, 0);
    }
}